// round 1
// baseline (speedup 1.0000x reference)
#include <cuda_runtime.h>
#include <mma.h>
#include <math.h>

using namespace nvcuda;

#define B_   4
#define T_   4096
#define D_   1024
#define H_   8
#define BS_  128
#define CT_  64
#define NC_  (T_/CT_)      /* 64 chunks */
#define CPG_ 4             /* chunks per block */
#define GBLKS_ (NC_/CPG_)  /* 16 */
#define WP_  132
#define ZP_  132

// Scratch (device globals: no allocation allowed)
__device__ __align__(16) float g_ylocal[B_*T_*D_];
__device__ __align__(16) float g_prefix[B_*T_*D_];
__device__ __align__(16) float g_Asum  [B_*NC_*D_];
__device__ __align__(16) float g_ylast [B_*NC_*D_];
__device__ __align__(16) float g_carry [B_*NC_*D_];

#define SMEM_FLOATS (2*128*WP_ + 2*CT_*ZP_ + 128)
#define SMEM_BYTES  (SMEM_FLOATS*4)

// ---------------------------------------------------------------------------
// K1: per (b, h, chunk-group): tf32 wmma GEMM for both gates, elementwise
// gate math, per-channel serial in-chunk scan. Writes y_local (zero-init scan),
// inclusive prefix products of a, and per-chunk (A_prod, y_last) summaries.
// ---------------------------------------------------------------------------
__global__ void __launch_bounds__(256, 1) k1_gates_scan(
    const float* __restrict__ x, const float* __restrict__ a_param,
    const float* __restrict__ w_in, const float* __restrict__ w_a)
{
    extern __shared__ float sm[];
    float* w1s = sm;                    // [128][WP_]
    float* w2s = w1s + 128*WP_;         // [128][WP_]
    float* z1  = w2s + 128*WP_;         // [CT_][ZP_]  (gate_in z -> a)
    float* z2  = z1  + CT_*ZP_;         // [CT_][ZP_]  (gate_a z  -> b)
    float* sps = z2  + CT_*ZP_;         // [128]  8*softplus(a_param)

    const int b  = blockIdx.z;
    const int h  = blockIdx.y;
    const int gb = blockIdx.x;
    const int tid = threadIdx.x;

    // Stage weights for this head (both gates) into smem, padded rows
    const float* w1g = w_in + h*BS_*BS_;
    const float* w2g = w_a  + h*BS_*BS_;
    for (int i = tid; i < BS_*BS_; i += 256) {
        int d = i >> 7, e = i & 127;
        w1s[d*WP_ + e] = w1g[i];
        w2s[d*WP_ + e] = w2g[i];
    }
    if (tid < 128) {
        float apv = a_param[h*BS_ + tid];
        sps[tid] = 8.0f * log1pf(__expf(apv));   // C * softplus(a_param)
    }
    __syncthreads();

    const int warp = tid >> 5;
    const int rb   = warp >> 1;   // 0..3: 16-row block
    const int chf  = warp & 1;    // 0..1: 64-col half

    for (int cc = 0; cc < CPG_; ++cc) {
        const int c  = gb*CPG_ + cc;
        const int t0 = c*CT_;

        wmma::fragment<wmma::accumulator, 16, 16, 8, float> acc1[4], acc2[4];
        #pragma unroll
        for (int j = 0; j < 4; ++j) {
            wmma::fill_fragment(acc1[j], 0.0f);
            wmma::fill_fragment(acc2[j], 0.0f);
        }

        const float* xA = x + ((size_t)(b*T_ + t0 + rb*16))*D_ + h*BS_;

        #pragma unroll 2
        for (int kk = 0; kk < 16; ++kk) {
            wmma::fragment<wmma::matrix_a, 16, 16, 8, wmma::precision::tf32, wmma::row_major> af;
            wmma::load_matrix_sync(af, xA + kk*8, D_);
            #pragma unroll
            for (int i = 0; i < af.num_elements; ++i) af.x[i] = wmma::__float_to_tf32(af.x[i]);

            #pragma unroll
            for (int j = 0; j < 4; ++j) {
                wmma::fragment<wmma::matrix_b, 16, 16, 8, wmma::precision::tf32, wmma::row_major> bf;
                wmma::load_matrix_sync(bf, w1s + kk*8*WP_ + chf*64 + j*16, WP_);
                #pragma unroll
                for (int i = 0; i < bf.num_elements; ++i) bf.x[i] = wmma::__float_to_tf32(bf.x[i]);
                wmma::mma_sync(acc1[j], af, bf, acc1[j]);
            }
            #pragma unroll
            for (int j = 0; j < 4; ++j) {
                wmma::fragment<wmma::matrix_b, 16, 16, 8, wmma::precision::tf32, wmma::row_major> bf;
                wmma::load_matrix_sync(bf, w2s + kk*8*WP_ + chf*64 + j*16, WP_);
                #pragma unroll
                for (int i = 0; i < bf.num_elements; ++i) bf.x[i] = wmma::__float_to_tf32(bf.x[i]);
                wmma::mma_sync(acc2[j], af, bf, acc2[j]);
            }
        }
        #pragma unroll
        for (int j = 0; j < 4; ++j) {
            wmma::store_matrix_sync(z1 + rb*16*ZP_ + chf*64 + j*16, acc1[j], ZP_, wmma::mem_row_major);
            wmma::store_matrix_sync(z2 + rb*16*ZP_ + chf*64 + j*16, acc2[j], ZP_, wmma::mem_row_major);
        }
        __syncthreads();

        // Elementwise: z -> (a, b)
        for (int idx = tid; idx < CT_*128; idx += 256) {
            int t = idx >> 7, e = idx & 127;
            float zin = z1[t*ZP_ + e];
            float za  = z2[t*ZP_ + e];
            float gi  = 1.0f / (1.0f + __expf(-zin));
            float ga  = 1.0f / (1.0f + __expf(-za));
            float la  = -sps[e] * ga;                    // log_a
            float a   = __expf(la);
            float m2  = -expm1f(2.0f*la);                // 1 - exp(2*log_a), accurate
            float mult = sqrtf(fmaxf(m2, 0.0f));
            float xv  = x[((size_t)(b*T_ + t0 + t))*D_ + h*BS_ + e];
            z1[t*ZP_ + e] = a;
            z2[t*ZP_ + e] = mult * gi * xv;
        }
        __syncthreads();

        // In-chunk serial scan (zero init) + inclusive prefix product of a
        if (tid < 128) {
            const int e = tid;
            float y = 0.0f, P = 1.0f;
            size_t base = ((size_t)(b*T_ + t0))*D_ + h*BS_ + e;
            #pragma unroll 8
            for (int t = 0; t < CT_; ++t) {
                float a  = z1[t*ZP_ + e];
                float bb = z2[t*ZP_ + e];
                y = fmaf(a, y, bb);
                P *= a;
                g_ylocal[base + (size_t)t*D_] = y;
                g_prefix[base + (size_t)t*D_] = P;
            }
            size_t si = ((size_t)(b*NC_ + c))*D_ + h*BS_ + e;
            g_Asum[si]  = P;
            g_ylast[si] = y;
        }
        __syncthreads();
    }
}

// ---------------------------------------------------------------------------
// K2: scan over chunk summaries. carry[c] = state entering chunk c.
// Also produces h_last = final state.
// ---------------------------------------------------------------------------
__global__ void k2_chunkscan(float* __restrict__ hlast_out)
{
    int g = blockIdx.x*blockDim.x + threadIdx.x;   // 0 .. B*D-1
    int b = g >> 10, d = g & 1023;
    float S = 0.0f;
    #pragma unroll 8
    for (int c = 0; c < NC_; ++c) {
        size_t i = ((size_t)(b*NC_ + c))*D_ + d;
        float A  = g_Asum[i];
        float yl = g_ylast[i];
        g_carry[i] = S;
        S = fmaf(A, S, yl);
    }
    hlast_out[g] = S;
}

// ---------------------------------------------------------------------------
// K3: y = y_local + carry * prefix   (fully parallel, float4)
// ---------------------------------------------------------------------------
__global__ void __launch_bounds__(256) k3_apply(float* __restrict__ y)
{
    size_t i4 = (size_t)blockIdx.x*256 + threadIdx.x;
    size_t i  = i4 * 4;
    int d = (int)(i % D_);
    int t = (int)((i / D_) % T_);
    int b = (int)(i / ((size_t)D_ * T_));
    int c = t / CT_;
    const float4 yl = *reinterpret_cast<const float4*>(g_ylocal + i);
    const float4 P  = *reinterpret_cast<const float4*>(g_prefix + i);
    const float4 S  = *reinterpret_cast<const float4*>(g_carry + ((size_t)(b*NC_ + c))*D_ + d);
    float4 r;
    r.x = fmaf(S.x, P.x, yl.x);
    r.y = fmaf(S.y, P.y, yl.y);
    r.z = fmaf(S.z, P.z, yl.z);
    r.w = fmaf(S.w, P.w, yl.w);
    *reinterpret_cast<float4*>(y + i) = r;
}

extern "C" void kernel_launch(void* const* d_in, const int* in_sizes, int n_in,
                              void* d_out, int out_size)
{
    const float* x  = (const float*)d_in[0];
    const float* ap = (const float*)d_in[1];
    const float* wi = (const float*)d_in[2];
    const float* wa = (const float*)d_in[3];
    float* out = (float*)d_out;

    cudaFuncSetAttribute(k1_gates_scan,
                         cudaFuncAttributeMaxDynamicSharedMemorySize, SMEM_BYTES);

    k1_gates_scan<<<dim3(GBLKS_, H_, B_), 256, SMEM_BYTES>>>(x, ap, wi, wa);
    k2_chunkscan<<<(B_*D_)/256, 256>>>(out + (size_t)B_*T_*D_);
    k3_apply<<<(B_*T_*D_)/(4*256), 256>>>(out);
}

// round 2
// speedup vs baseline: 1.2238x; 1.2238x over previous
#include <cuda_runtime.h>
#include <mma.h>
#include <math.h>

using namespace nvcuda;

#define B_   4
#define T_   4096
#define D_   1024
#define H_   8
#define BS_  128
#define CT_  64              /* GEMM chunk (timesteps per GEMM round) */
#define SEG_ 16              /* scan segment length (the "chunk" for carry machinery) */
#define NSEG_ (CT_/SEG_)     /* 4 */
#define NC2_ (T_/SEG_)       /* 256 scan chunks */
#define CPG_ 4               /* GEMM chunks per block (256 timesteps) */
#define GBLKS_ ((T_/CT_)/CPG_)  /* 16 */
#define WP_  68              /* padded width for 64-col weight/z tiles */

// Scratch (device globals: no allocation allowed)
__device__ __align__(16) float g_ylocal[B_*T_*D_];
__device__ __align__(16) float g_prefix[B_*T_*D_];
__device__ __align__(16) float g_Asum  [B_*NC2_*D_];
__device__ __align__(16) float g_ylast [B_*NC2_*D_];
__device__ __align__(16) float g_carry [B_*NC2_*D_];

#define SMEM_FLOATS (2*128*WP_ + 2*CT_*WP_ + 64)
#define SMEM_BYTES  (SMEM_FLOATS*4)   /* 104,704 B -> 2 CTAs/SM */

// ---------------------------------------------------------------------------
// K1: block = (b, h, half[64 cols], chunk-group of 4x64 timesteps).
// tf32 wmma GEMM (K=128, N=64, M=64 per round) for both gates, elementwise
// gate math, then 16-step segment scans using ALL 256 threads.
// ---------------------------------------------------------------------------
__global__ void __launch_bounds__(256, 2) k1_gates_scan(
    const float* __restrict__ x, const float* __restrict__ a_param,
    const float* __restrict__ w_in, const float* __restrict__ w_a)
{
    extern __shared__ float sm[];
    float* w1s = sm;                    // [128][WP_]  (K x 64N, pre-rounded tf32)
    float* w2s = w1s + 128*WP_;         // [128][WP_]
    float* z1  = w2s + 128*WP_;         // [CT_][WP_]
    float* z2  = z1  + CT_*WP_;         // [CT_][WP_]
    float* sps = z2  + CT_*WP_;         // [64]

    const int b    = blockIdx.z;
    const int h    = blockIdx.y >> 1;
    const int half = blockIdx.y & 1;
    const int gb   = blockIdx.x;
    const int tid  = threadIdx.x;
    const int col0 = h*BS_ + half*64;   // first global channel of this block

    // Stage this block's 64 output columns of both weight matrices, tf32-rounded.
    // w layout: [H][bs(in,d)][bs(out,e)] row-major -> element (d, e) at d*128+e.
    {
        const float* w1g = w_in + (size_t)h*BS_*BS_ + half*64;
        const float* w2g = w_a  + (size_t)h*BS_*BS_ + half*64;
        for (int i = tid; i < 128*64; i += 256) {
            int d = i >> 6, e = i & 63;
            w1s[d*WP_ + e] = wmma::__float_to_tf32(w1g[(size_t)d*BS_ + e]);
            w2s[d*WP_ + e] = wmma::__float_to_tf32(w2g[(size_t)d*BS_ + e]);
        }
        if (tid < 64) {
            float apv = a_param[col0 + tid];
            sps[tid] = 8.0f * log1pf(__expf(apv));   // C * softplus(a_param)
        }
    }
    __syncthreads();

    const int warp = tid >> 5;
    const int rb   = warp >> 1;   // 0..3: 16-row block of M=64
    const int chf  = warp & 1;    // 0..1: 32-col half of N=64

    for (int cc = 0; cc < CPG_; ++cc) {
        const int t0 = (gb*CPG_ + cc)*CT_;

        wmma::fragment<wmma::accumulator, 16, 16, 8, float> acc1[2], acc2[2];
        #pragma unroll
        for (int j = 0; j < 2; ++j) {
            wmma::fill_fragment(acc1[j], 0.0f);
            wmma::fill_fragment(acc2[j], 0.0f);
        }

        const float* xA = x + ((size_t)(b*T_ + t0 + rb*16))*D_ + h*BS_;

        #pragma unroll 4
        for (int kk = 0; kk < 16; ++kk) {
            wmma::fragment<wmma::matrix_a, 16, 16, 8, wmma::precision::tf32, wmma::row_major> af;
            wmma::load_matrix_sync(af, xA + kk*8, D_);
            #pragma unroll
            for (int i = 0; i < af.num_elements; ++i) af.x[i] = wmma::__float_to_tf32(af.x[i]);

            #pragma unroll
            for (int j = 0; j < 2; ++j) {
                wmma::fragment<wmma::matrix_b, 16, 16, 8, wmma::precision::tf32, wmma::row_major> bf;
                wmma::load_matrix_sync(bf, w1s + kk*8*WP_ + chf*32 + j*16, WP_);
                wmma::mma_sync(acc1[j], af, bf, acc1[j]);
            }
            #pragma unroll
            for (int j = 0; j < 2; ++j) {
                wmma::fragment<wmma::matrix_b, 16, 16, 8, wmma::precision::tf32, wmma::row_major> bf;
                wmma::load_matrix_sync(bf, w2s + kk*8*WP_ + chf*32 + j*16, WP_);
                wmma::mma_sync(acc2[j], af, bf, acc2[j]);
            }
        }
        #pragma unroll
        for (int j = 0; j < 2; ++j) {
            wmma::store_matrix_sync(z1 + rb*16*WP_ + chf*32 + j*16, acc1[j], WP_, wmma::mem_row_major);
            wmma::store_matrix_sync(z2 + rb*16*WP_ + chf*32 + j*16, acc2[j], WP_, wmma::mem_row_major);
        }
        __syncthreads();

        // Elementwise: z -> (a, mult*gate_x*x); 64t x 64e, 16 per thread
        #pragma unroll 4
        for (int idx = tid; idx < CT_*64; idx += 256) {
            int t = idx >> 6, e = idx & 63;
            float zin = z1[t*WP_ + e];
            float za  = z2[t*WP_ + e];
            float gi  = 1.0f / (1.0f + __expf(-zin));
            float ga  = 1.0f / (1.0f + __expf(-za));
            float la  = -sps[e] * ga;                    // log_a
            float a   = __expf(la);
            float m2  = -expm1f(2.0f*la);                // 1 - exp(2*log_a), accurate
            float mult = sqrtf(fmaxf(m2, 0.0f));
            float xv  = x[((size_t)(b*T_ + t0 + t))*D_ + col0 + e];
            z1[t*WP_ + e] = a;
            z2[t*WP_ + e] = mult * gi * xv;
        }
        __syncthreads();

        // Segment scans: all 256 threads = 64 channels x 4 segments of 16 steps
        {
            const int e   = tid & 63;
            const int seg = tid >> 6;
            float y = 0.0f, P = 1.0f;
            size_t base = ((size_t)(b*T_ + t0 + seg*SEG_))*D_ + col0 + e;
            const float* z1p = z1 + (seg*SEG_)*WP_ + e;
            const float* z2p = z2 + (seg*SEG_)*WP_ + e;
            #pragma unroll
            for (int t = 0; t < SEG_; ++t) {
                float a  = z1p[t*WP_];
                float bb = z2p[t*WP_];
                y = fmaf(a, y, bb);
                P *= a;
                g_ylocal[base + (size_t)t*D_] = y;
                g_prefix[base + (size_t)t*D_] = P;
            }
            int c2 = t0/SEG_ + seg;
            size_t si = ((size_t)(b*NC2_ + c2))*D_ + col0 + e;
            g_Asum[si]  = P;
            g_ylast[si] = y;
        }
        __syncthreads();
    }
}

// ---------------------------------------------------------------------------
// K2: serial scan over 256 chunk summaries per channel; emits carries + h_last
// ---------------------------------------------------------------------------
__global__ void __launch_bounds__(256) k2_chunkscan(float* __restrict__ hlast_out)
{
    int g = blockIdx.x*blockDim.x + threadIdx.x;   // 0 .. B*D-1
    int b = g >> 10, d = g & 1023;
    float S = 0.0f;
    size_t base = (size_t)b*NC2_*D_ + d;
    #pragma unroll 8
    for (int c = 0; c < NC2_; ++c) {
        size_t i = base + (size_t)c*D_;
        float A  = g_Asum[i];
        float yl = g_ylast[i];
        g_carry[i] = S;
        S = fmaf(A, S, yl);
    }
    hlast_out[g] = S;
}

// ---------------------------------------------------------------------------
// K3: y = y_local + carry * prefix   (fully parallel, float4)
// ---------------------------------------------------------------------------
__global__ void __launch_bounds__(256) k3_apply(float* __restrict__ y)
{
    size_t i4 = (size_t)blockIdx.x*256 + threadIdx.x;
    size_t i  = i4 * 4;
    int d = (int)(i % D_);
    int t = (int)((i / D_) % T_);
    int b = (int)(i / ((size_t)D_ * T_));
    int c = t / SEG_;
    const float4 yl = *reinterpret_cast<const float4*>(g_ylocal + i);
    const float4 P  = *reinterpret_cast<const float4*>(g_prefix + i);
    const float4 S  = *reinterpret_cast<const float4*>(g_carry + ((size_t)(b*NC2_ + c))*D_ + d);
    float4 r;
    r.x = fmaf(S.x, P.x, yl.x);
    r.y = fmaf(S.y, P.y, yl.y);
    r.z = fmaf(S.z, P.z, yl.z);
    r.w = fmaf(S.w, P.w, yl.w);
    *reinterpret_cast<float4*>(y + i) = r;
}

extern "C" void kernel_launch(void* const* d_in, const int* in_sizes, int n_in,
                              void* d_out, int out_size)
{
    const float* x  = (const float*)d_in[0];
    const float* ap = (const float*)d_in[1];
    const float* wi = (const float*)d_in[2];
    const float* wa = (const float*)d_in[3];
    float* out = (float*)d_out;

    cudaFuncSetAttribute(k1_gates_scan,
                         cudaFuncAttributeMaxDynamicSharedMemorySize, SMEM_BYTES);

    k1_gates_scan<<<dim3(GBLKS_, H_*2, B_), 256, SMEM_BYTES>>>(x, ap, wi, wa);
    k2_chunkscan<<<(B_*D_)/256, 256>>>(out + (size_t)B_*T_*D_);
    k3_apply<<<(B_*T_*D_)/(4*256), 256>>>(out);
}

// round 3
// speedup vs baseline: 1.5174x; 1.2400x over previous
#include <cuda_runtime.h>
#include <mma.h>
#include <math.h>

using namespace nvcuda;

#define B_   4
#define T_   4096
#define D_   1024
#define H_   8
#define BS_  128
#define TB_  256             /* timesteps per block (chain link) */
#define SC_  32              /* timesteps per GEMM sub-chunk */
#define NSC_ (TB_/SC_)       /* 8 */
#define SEG_ 8               /* scan segment */
#define NSEG_ (SC_/SEG_)     /* 4 */
#define NGB_ (T_/TB_)        /* 16 chain links */
#define WP_  68              /* padded width, weight/z tiles (68*4B mult of 16) */
#define XP_  132             /* padded width, x tile */

// Scratch (device globals; no allocation allowed)
__device__ __align__(16) float g_ylocal[B_*T_*D_];
__device__ __align__(16) float g_prefix[B_*T_*D_];
__device__ __align__(16) float g_state [B_*16*NGB_*64];
__device__ int   g_flag  [B_*16*NGB_];

// smem layout (floats)
#define OFF_W1   0
#define OFF_W2   (OFF_W1 + 128*WP_)          /* 8704 */
#define OFF_XS   (OFF_W2 + 128*WP_)          /* 17408 */
#define OFF_Z1   (OFF_XS + SC_*XP_)          /* 21632 */
#define OFF_Z2   (OFF_Z1 + SC_*WP_)          /* 23808 */
#define OFF_SPS  (OFF_Z2 + SC_*WP_)          /* 25984 */
#define OFF_RUNY (OFF_SPS + 64)
#define OFF_RUNA (OFF_RUNY + 64)
#define OFF_SEGA (OFF_RUNA + 64)
#define OFF_SEGY (OFF_SEGA + NSEG_*64)
#define OFF_SSA  (OFF_SEGY + NSEG_*64)
#define OFF_SSY  (OFF_SSA + NSEG_*64)
#define OFF_SIN  (OFF_SSY + NSEG_*64)
#define SMEM_FLOATS (OFF_SIN + 64)
#define SMEM_BYTES (SMEM_FLOATS*4)           /* ~109 KB -> 2 CTAs/SM */

__global__ void k0_reset() {
    int i = blockIdx.x*blockDim.x + threadIdx.x;
    if (i < B_*16*NGB_) g_flag[i] = 0;
}

// ---------------------------------------------------------------------------
// Fused: block = (gb chain link, (h,half), b). GEMM both gates (tf32 wmma,
// A staged in smem), gate math, segment scan, decoupled-lookback carry,
// in-place carry apply, y + h_last written directly.
// ---------------------------------------------------------------------------
__global__ void __launch_bounds__(256, 2) k1_fused(
    const float* __restrict__ x, const float* __restrict__ a_param,
    const float* __restrict__ w_in, const float* __restrict__ w_a,
    float* __restrict__ out)
{
    extern __shared__ float sm[];
    float* w1s  = sm + OFF_W1;
    float* w2s  = sm + OFF_W2;
    float* xs   = sm + OFF_XS;
    float* z1   = sm + OFF_Z1;
    float* z2   = sm + OFF_Z2;
    float* sps  = sm + OFF_SPS;
    float* runY = sm + OFF_RUNY;
    float* runA = sm + OFF_RUNA;
    float* segA = sm + OFF_SEGA;
    float* segY = sm + OFF_SEGY;
    float* ssA  = sm + OFF_SSA;
    float* ssY  = sm + OFF_SSY;
    float* Sin  = sm + OFF_SIN;

    const int b    = blockIdx.z;
    const int h    = blockIdx.y >> 1;
    const int half = blockIdx.y & 1;
    const int gb   = blockIdx.x;
    const int tid  = threadIdx.x;
    const int col0 = h*BS_ + half*64;
    const int t0   = gb*TB_;

    // Stage weights (64 output cols of both gates), tf32 pre-rounded
    {
        const float* w1g = w_in + (size_t)h*BS_*BS_ + half*64;
        const float* w2g = w_a  + (size_t)h*BS_*BS_ + half*64;
        for (int i = tid; i < 128*64; i += 256) {
            int d = i >> 6, e = i & 63;
            w1s[d*WP_ + e] = wmma::__float_to_tf32(w1g[(size_t)d*BS_ + e]);
            w2s[d*WP_ + e] = wmma::__float_to_tf32(w2g[(size_t)d*BS_ + e]);
        }
        if (tid < 64) {
            float apv = a_param[col0 + tid];
            sps[tid]  = 8.0f * log1pf(__expf(apv));    // C * softplus
            runY[tid] = 0.0f;
            runA[tid] = 1.0f;
        }
    }

    const int warp = tid >> 5;
    const int rb   = warp >> 2;   // 0..1: 16-row block of M=32
    const int cq   = warp & 3;    // 0..3: 16-col quarter of N=64
    const int e    = tid & 63;    // scan channel
    const int sg   = tid >> 6;    // scan segment 0..3

    __syncthreads();

    for (int cc = 0; cc < NSC_; ++cc) {
        const int ts = t0 + cc*SC_;   // first timestep of sub-chunk

        // ---- stage x tile [SC_][128] (coalesced float4) ----
        {
            const float* xg = x + ((size_t)(b*T_ + ts))*D_ + h*BS_;
            #pragma unroll
            for (int q = tid; q < SC_*32; q += 256) {
                int t = q >> 5, c4 = (q & 31) << 2;
                float4 v = *reinterpret_cast<const float4*>(xg + (size_t)t*D_ + c4);
                *reinterpret_cast<float4*>(xs + t*XP_ + c4) = v;
            }
        }
        __syncthreads();

        // ---- GEMM: M=32, N=64, K=128, both gates ----
        {
            wmma::fragment<wmma::accumulator, 16, 16, 8, float> acc1, acc2;
            wmma::fill_fragment(acc1, 0.0f);
            wmma::fill_fragment(acc2, 0.0f);
            const float* xb = xs + rb*16*XP_;
            #pragma unroll 4
            for (int kk = 0; kk < 16; ++kk) {
                wmma::fragment<wmma::matrix_a, 16, 16, 8, wmma::precision::tf32, wmma::row_major> af;
                wmma::load_matrix_sync(af, xb + kk*8, XP_);
                #pragma unroll
                for (int i = 0; i < af.num_elements; ++i) af.x[i] = wmma::__float_to_tf32(af.x[i]);
                wmma::fragment<wmma::matrix_b, 16, 16, 8, wmma::precision::tf32, wmma::row_major> bf;
                wmma::load_matrix_sync(bf, w1s + kk*8*WP_ + cq*16, WP_);
                wmma::mma_sync(acc1, af, bf, acc1);
                wmma::load_matrix_sync(bf, w2s + kk*8*WP_ + cq*16, WP_);
                wmma::mma_sync(acc2, af, bf, acc2);
            }
            wmma::store_matrix_sync(z1 + rb*16*WP_ + cq*16, acc1, WP_, wmma::mem_row_major);
            wmma::store_matrix_sync(z2 + rb*16*WP_ + cq*16, acc2, WP_, wmma::mem_row_major);
        }
        __syncthreads();

        // ---- elementwise: z -> (a, mult*gate_x*x) ----
        #pragma unroll
        for (int idx = tid; idx < SC_*64; idx += 256) {
            int t = idx >> 6, ee = idx & 63;
            float zin = z1[t*WP_ + ee];
            float za  = z2[t*WP_ + ee];
            float gi  = 1.0f / (1.0f + __expf(-zin));
            float ga  = 1.0f / (1.0f + __expf(-za));
            float la  = -sps[ee] * ga;
            float a   = __expf(la);
            float m2  = -expm1f(2.0f*la);
            float mult = sqrtf(fmaxf(m2, 0.0f));
            float xv  = xs[t*XP_ + half*64 + ee];
            z1[t*WP_ + ee] = a;
            z2[t*WP_ + ee] = mult * gi * xv;
        }
        __syncthreads();

        // ---- pass1: segment summaries (8 steps each) ----
        {
            float P = 1.0f, y = 0.0f;
            const float* z1p = z1 + (sg*SEG_)*WP_ + e;
            const float* z2p = z2 + (sg*SEG_)*WP_ + e;
            #pragma unroll
            for (int t = 0; t < SEG_; ++t) {
                float a  = z1p[t*WP_];
                float bb = z2p[t*WP_];
                y = fmaf(a, y, bb);
                P *= a;
            }
            segA[sg*64 + e] = P;
            segY[sg*64 + e] = y;
        }
        __syncthreads();

        // ---- pass2: serial seg-start combine (per channel) ----
        if (tid < 64) {
            float Yr = runY[tid], Ar = runA[tid];
            #pragma unroll
            for (int s = 0; s < NSEG_; ++s) {
                ssY[s*64 + tid] = Yr;
                ssA[s*64 + tid] = Ar;
                float As = segA[s*64 + tid];
                Yr = fmaf(As, Yr, segY[s*64 + tid]);
                Ar *= As;
            }
            runY[tid] = Yr;
            runA[tid] = Ar;
        }
        __syncthreads();

        // ---- pass3: rescan, write block-relative y_local & prefix ----
        {
            float y = ssY[sg*64 + e];
            float P = ssA[sg*64 + e];
            const float* z1p = z1 + (sg*SEG_)*WP_ + e;
            const float* z2p = z2 + (sg*SEG_)*WP_ + e;
            size_t base = ((size_t)(b*T_ + ts + sg*SEG_))*D_ + col0 + e;
            #pragma unroll
            for (int t = 0; t < SEG_; ++t) {
                float a  = z1p[t*WP_];
                float bb = z2p[t*WP_];
                y = fmaf(a, y, bb);
                P *= a;
                g_ylocal[base + (size_t)t*D_] = y;
                g_prefix[base + (size_t)t*D_] = P;
            }
        }
        __syncthreads();
    }

    // ---- decoupled lookback ----
    const int cidx = (b*16 + blockIdx.y)*NGB_ + gb;
    if (gb > 0 && tid == 0) {
        while (atomicAdd(&g_flag[cidx-1], 0) == 0) { __nanosleep(32); }
        __threadfence();   // cumulative acquire for the whole block
    }
    __syncthreads();
    if (tid < 64) {
        float s_in = 0.0f;
        if (gb > 0) {
            volatile const float* st = g_state + (size_t)(cidx-1)*64;
            s_in = st[tid];
        }
        Sin[tid] = s_in;
        float s_out = fmaf(runA[tid], s_in, runY[tid]);
        volatile float* stc = g_state + (size_t)cidx*64;
        stc[tid] = s_out;
        if (gb == NGB_-1) out[(size_t)B_*T_*D_ + b*D_ + col0 + tid] = s_out;
    }
    __syncthreads();
    if (tid == 0) {
        __threadfence();   // cumulative: orders peer writes (via barrier) before flag
        atomicExch(&g_flag[cidx], 1);
    }

    // ---- carry apply: y = y_local + S_in * prefix (L2-hot re-read) ----
    {
        float4 S4;
        // per-thread channel quad
        const int c4 = (tid & 15) << 2;
        S4.x = Sin[c4+0]; S4.y = Sin[c4+1]; S4.z = Sin[c4+2]; S4.w = Sin[c4+3];
        #pragma unroll 4
        for (int q = tid; q < TB_*16; q += 256) {
            int t  = q >> 4;
            int cq4 = (q & 15) << 2;
            float4 S = S4;
            if (cq4 != c4) { S.x = Sin[cq4]; S.y = Sin[cq4+1]; S.z = Sin[cq4+2]; S.w = Sin[cq4+3]; }
            size_t i = ((size_t)(b*T_ + t0 + t))*D_ + col0 + cq4;
            const float4 yl = *reinterpret_cast<const float4*>(g_ylocal + i);
            const float4 P  = *reinterpret_cast<const float4*>(g_prefix + i);
            float4 r;
            r.x = fmaf(S.x, P.x, yl.x);
            r.y = fmaf(S.y, P.y, yl.y);
            r.z = fmaf(S.z, P.z, yl.z);
            r.w = fmaf(S.w, P.w, yl.w);
            *reinterpret_cast<float4*>(out + i) = r;
        }
    }
}

extern "C" void kernel_launch(void* const* d_in, const int* in_sizes, int n_in,
                              void* d_out, int out_size)
{
    const float* x  = (const float*)d_in[0];
    const float* ap = (const float*)d_in[1];
    const float* wi = (const float*)d_in[2];
    const float* wa = (const float*)d_in[3];
    float* out = (float*)d_out;

    cudaFuncSetAttribute(k1_fused,
                         cudaFuncAttributeMaxDynamicSharedMemorySize, SMEM_BYTES);

    k0_reset<<<1, 1024>>>();
    k1_fused<<<dim3(NGB_, 16, B_), 256, SMEM_BYTES>>>(x, ap, wi, wa, out);
}

// round 9
// speedup vs baseline: 1.6027x; 1.0562x over previous
#include <cuda_runtime.h>
#include <cstdint>
#include <mma.h>
#include <math.h>

using namespace nvcuda;

#define B_   4
#define T_   4096
#define D_   1024
#define H_   8
#define BS_  128
#define TB_  2048            /* timesteps per block (half of T) */
#define SC_  32              /* timesteps per GEMM sub-chunk */
#define NSC_ (TB_/SC_)       /* 64 */
#define NCB_ 32              /* channel-blocks: H * 4 quarters */
#define WP_  36              /* weight tile row stride */
#define ZPT_ 36              /* z tile (channel-major) row stride */
#define XP_  132             /* x tile row stride */

// Scratch (device globals; no allocation allowed). No flags, no spins.
__device__ __align__(16) float g_ylocal[B_*T_*D_];   /* second half only */
__device__ __align__(16) float g_prefix[B_*T_*D_];
__device__ __align__(16) float g_S0[B_*D_];          /* state after first half */
__device__ __align__(16) float g_hP[B_*D_];          /* A-product of second half */
__device__ __align__(16) float g_hY[B_*D_];          /* local Y of second half */

// smem layout (floats)
#define OFF_W1   0
#define OFF_W2   (OFF_W1 + 128*WP_)     /* 4608  */
#define OFF_XS0  (OFF_W2 + 128*WP_)     /* 9216  */
#define OFF_XS1  (OFF_XS0 + SC_*XP_)    /* 13440 */
#define OFF_Z1   (OFF_XS1 + SC_*XP_)    /* 17664 */
#define OFF_Z2   (OFF_Z1 + 32*ZPT_)     /* 18816 */
#define OFF_SPS  (OFF_Z2 + 32*ZPT_)     /* 19968 */
#define SMEM_FLOATS (OFF_SPS + 32)      /* 20000 -> 78.1 KB -> 2 CTAs/SM */
#define SMEM_BYTES  (SMEM_FLOATS*4)

__device__ __forceinline__ void cp16(unsigned dst, const float* src) {
    asm volatile("cp.async.cg.shared.global [%0], [%1], 16;" :: "r"(dst), "l"(src));
}

// ---------------------------------------------------------------------------
// K1: block = (gb time-half, channel-block, batch). 32 channels, 2048 steps.
// No inter-block communication of any kind.
// ---------------------------------------------------------------------------
__global__ void __launch_bounds__(256, 2) k1_gemm_scan(
    const float* __restrict__ x, const float* __restrict__ a_param,
    const float* __restrict__ w_in, const float* __restrict__ w_a,
    float* __restrict__ out)
{
    extern __shared__ float sm[];
    float* w1s = sm + OFF_W1;
    float* w2s = sm + OFF_W2;
    float* z1  = sm + OFF_Z1;    // [32 ch][ZPT_] gate_x z (channel-major)
    float* z2  = sm + OFF_Z2;    // [32 ch][ZPT_] gate_a z
    float* sps = sm + OFF_SPS;

    const int b    = blockIdx.z;
    const int cb   = blockIdx.y;
    const int h    = cb >> 2;
    const int q    = cb & 3;
    const int gb   = blockIdx.x;          // 0 or 1
    const int tid  = threadIdx.x;
    const int col0 = h*BS_ + q*32;
    const int t0   = gb*TB_;

    // Stage weights (32 output cols of both gates), tf32 pre-rounded
    {
        const float* w1g = w_in + (size_t)h*BS_*BS_ + q*32;
        const float* w2g = w_a  + (size_t)h*BS_*BS_ + q*32;
        for (int i = tid; i < 128*32; i += 256) {
            int d = i >> 5, e = i & 31;
            w1s[d*WP_ + e] = wmma::__float_to_tf32(w1g[d*BS_ + e]);
            w2s[d*WP_ + e] = wmma::__float_to_tf32(w2g[d*BS_ + e]);
        }
        if (tid < 32) {
            float apv = a_param[col0 + tid];
            sps[tid]  = 8.0f * log1pf(__expf(apv));   // C * softplus(a_param)
        }
    }

    const int warp = tid >> 5;
    const int lane = tid & 31;
    // GEMM mapping
    const int g    = warp >> 2;        // gate 0/1
    const int rb   = (warp >> 1) & 1;  // 16-row block of M=32
    const int cq   = warp & 1;         // 16-col half of N=32
    float* wg = g ? w2s : w1s;
    float* zg = g ? z2  : z1;
    // scan mapping: lane = el*8 + sg ; channel e = warp*4 + el
    const int el = lane >> 3;
    const int sg = lane & 7;
    const int e  = warp*4 + el;

    const float* xg_base = x + ((size_t)(b*T_ + t0))*D_ + h*BS_;
    unsigned xsb[2];
    xsb[0] = (unsigned)__cvta_generic_to_shared(sm + OFF_XS0);
    xsb[1] = (unsigned)__cvta_generic_to_shared(sm + OFF_XS1);
    float* xsf[2] = { sm + OFF_XS0, sm + OFF_XS1 };

    __syncthreads();
    const float spe = sps[e];

    // preload tile 0 into buf 0
    {
        #pragma unroll
        for (int k = 0; k < 4; ++k) {
            int qq = tid + 256*k;
            int t  = qq >> 5, c4 = (qq & 31) << 2;
            cp16(xsb[0] + (unsigned)(t*XP_ + c4)*4u, xg_base + (size_t)t*D_ + c4);
        }
        asm volatile("cp.async.commit_group;");
    }

    float s_sub = 0.0f;   // block-relative state
    float P_sub = 1.0f;   // running prefix product

    for (int cc = 0; cc < NSC_; ++cc) {
        const int buf = cc & 1;
        const int ts  = cc*SC_;    // block-relative first timestep

        __syncthreads();   // S1: prev scan done (other x buffer free)

        if (cc + 1 < NSC_) {
            const float* xg = xg_base + (size_t)(ts + SC_)*D_;
            #pragma unroll
            for (int k = 0; k < 4; ++k) {
                int qq = tid + 256*k;
                int t  = qq >> 5, c4 = (qq & 31) << 2;
                cp16(xsb[buf^1] + (unsigned)(t*XP_ + c4)*4u, xg + (size_t)t*D_ + c4);
            }
            asm volatile("cp.async.commit_group;");
            asm volatile("cp.async.wait_group 1;");
        } else {
            asm volatile("cp.async.wait_group 0;");
        }
        __syncthreads();   // S2: tile cc visible

        // ---- GEMM: M=32, N=32, K=128; warps split across gates ----
        {
            wmma::fragment<wmma::accumulator, 16, 16, 8, float> acc;
            wmma::fill_fragment(acc, 0.0f);
            const float* xb = xsf[buf] + rb*16*XP_;
            #pragma unroll 4
            for (int kk = 0; kk < 16; ++kk) {
                wmma::fragment<wmma::matrix_a, 16, 16, 8, wmma::precision::tf32, wmma::row_major> af;
                wmma::load_matrix_sync(af, xb + kk*8, XP_);
                #pragma unroll
                for (int i = 0; i < af.num_elements; ++i) af.x[i] = wmma::__float_to_tf32(af.x[i]);
                wmma::fragment<wmma::matrix_b, 16, 16, 8, wmma::precision::tf32, wmma::row_major> bf;
                wmma::load_matrix_sync(bf, wg + kk*8*WP_ + cq*16, WP_);
                wmma::mma_sync(acc, af, bf, acc);
            }
            // channel-major store: z[e][t]
            wmma::store_matrix_sync(zg + (cq*16)*ZPT_ + rb*16, acc, ZPT_, wmma::mem_col_major);
        }
        __syncthreads();   // S3

        // ---- scan lane work: 1 channel x 4 timesteps ----
        {
            const float4 zx4 = *reinterpret_cast<const float4*>(z1 + e*ZPT_ + sg*4);
            const float4 za4 = *reinterpret_cast<const float4*>(z2 + e*ZPT_ + sg*4);
            const float* xvp = xsf[buf] + (sg*4)*XP_ + q*32 + e;

            float av[4], bv[4];
            float Pseg = 1.0f, Yseg = 0.0f;
            const float zx[4] = {zx4.x, zx4.y, zx4.z, zx4.w};
            const float za[4] = {za4.x, za4.y, za4.z, za4.w};
            #pragma unroll
            for (int i = 0; i < 4; ++i) {
                float gi = __fdividef(1.0f, 1.0f + __expf(-zx[i]));
                float ga = __fdividef(1.0f, 1.0f + __expf(-za[i]));
                float la = -spe * ga;
                float a  = __expf(la);
                float m2 = -expm1f(2.0f*la);          // 1 - exp(2*la), accurate
                float mult = sqrtf(fmaxf(m2, 0.0f));
                float bb = mult * gi * xvp[i*XP_];
                av[i] = a; bv[i] = bb;
                Yseg = fmaf(a, Yseg, bb);
                Pseg *= a;
            }
            // Kogge-Stone over 8 segments (width-8 shuffles)
            float Ac = Pseg, Yc = Yseg;
            #pragma unroll
            for (int d = 1; d < 8; d <<= 1) {
                float Ap = __shfl_up_sync(0xffffffffu, Ac, d, 8);
                float Yp = __shfl_up_sync(0xffffffffu, Yc, d, 8);
                if (sg >= d) { Yc = fmaf(Ac, Yp, Yc); Ac *= Ap; }
            }
            float Aex = __shfl_up_sync(0xffffffffu, Ac, 1, 8);
            float Yex = __shfl_up_sync(0xffffffffu, Yc, 1, 8);
            if (sg == 0) { Aex = 1.0f; Yex = 0.0f; }
            const float At = __shfl_sync(0xffffffffu, Ac, 7, 8);
            const float Yt = __shfl_sync(0xffffffffu, Yc, 7, 8);

            float s = fmaf(Aex, s_sub, Yex);
            float P = P_sub * Aex;
            const size_t gbase = ((size_t)(b*T_ + t0 + ts + sg*4))*D_ + col0 + e;
            if (gb == 0) {
                #pragma unroll
                for (int i = 0; i < 4; ++i) {
                    s = fmaf(av[i], s, bv[i]);
                    out[gbase + (size_t)i*D_] = s;    // carry-in is 0: y == local
                }
            } else {
                #pragma unroll
                for (int i = 0; i < 4; ++i) {
                    s = fmaf(av[i], s, bv[i]);
                    P *= av[i];
                    g_ylocal[gbase + (size_t)i*D_] = s;
                    g_prefix[gbase + (size_t)i*D_] = P;
                }
            }
            s_sub = fmaf(At, s_sub, Yt);
            P_sub *= At;
        }
    }

    // publish summaries (no waiting, no flags)
    if (sg == 0) {
        const int gi = b*D_ + col0 + e;
        if (gb == 0) {
            g_S0[gi] = s_sub;                 // state entering second half
        } else {
            g_hP[gi] = P_sub;                 // A-product of second half
            g_hY[gi] = s_sub;                 // local Y of second half
        }
    }
}

// ---------------------------------------------------------------------------
// K2: h_last = A1 * S0 + Y1  (4096 channels)
// ---------------------------------------------------------------------------
__global__ void k2_hlast(float* __restrict__ out)
{
    int i = blockIdx.x*blockDim.x + threadIdx.x;   // 0 .. B*D-1
    out[(size_t)B_*T_*D_ + i] = fmaf(g_hP[i], g_S0[i], g_hY[i]);
}

// ---------------------------------------------------------------------------
// K3: second half only: y = y_local + S0 * prefix  (float4 streaming)
// ---------------------------------------------------------------------------
__global__ void __launch_bounds__(256) k3_apply(float* __restrict__ out)
{
    size_t j = (size_t)blockIdx.x*256 + threadIdx.x;   // over B*(T/2)*(D/4)
    int d4   = (int)(j & 255);                          // D/4 = 256
    size_t r = j >> 8;
    int t    = (int)(r & 2047) + TB_;                   // second half
    int b    = (int)(r >> 11);
    size_t i = ((size_t)(b*T_ + t))*D_ + d4*4;
    const float4 S  = *reinterpret_cast<const float4*>(g_S0 + b*D_ + d4*4);
    const float4 yl = *reinterpret_cast<const float4*>(g_ylocal + i);
    const float4 P  = *reinterpret_cast<const float4*>(g_prefix + i);
    float4 rr;
    rr.x = fmaf(S.x, P.x, yl.x);
    rr.y = fmaf(S.y, P.y, yl.y);
    rr.z = fmaf(S.z, P.z, yl.z);
    rr.w = fmaf(S.w, P.w, yl.w);
    *reinterpret_cast<float4*>(out + i) = rr;
}

extern "C" void kernel_launch(void* const* d_in, const int* in_sizes, int n_in,
                              void* d_out, int out_size)
{
    const float* x  = (const float*)d_in[0];
    const float* ap = (const float*)d_in[1];
    const float* wi = (const float*)d_in[2];
    const float* wa = (const float*)d_in[3];
    float* out = (float*)d_out;

    cudaFuncSetAttribute(k1_gemm_scan,
                         cudaFuncAttributeMaxDynamicSharedMemorySize, SMEM_BYTES);

    k1_gemm_scan<<<dim3(2, NCB_, B_), 256, SMEM_BYTES>>>(x, ap, wi, wa, out);
    k2_hlast<<<(B_*D_)/256, 256>>>(out);
    k3_apply<<<(B_*(T_/2)*(D_/4))/256, 256>>>(out);
}